// round 1
// baseline (speedup 1.0000x reference)
#include <cuda_runtime.h>
#include <cstdint>

#define BB 16
#define SS 2048
#define DD 512
#define CC 8192
// tokens
#define MM (BB * SS)

// ---------------------------------------------------------------------------
// Scratch: 0.5 * ||embed[c]||^2 per code (32 KB)
// ---------------------------------------------------------------------------
__device__ float g_half_e2[CC];

// One warp per code. grid = CC/8 blocks of 256 threads (8 warps).
__global__ void half_e2_kernel(const float* __restrict__ embed) {
    int c = blockIdx.x * 8 + (threadIdx.x >> 5);
    int lane = threadIdx.x & 31;
    const float4* e4 = (const float4*)embed;
    float s = 0.f;
#pragma unroll
    for (int j = 0; j < 4; j++) {
        float4 v = e4[(size_t)c * (DD / 4) + j * 32 + lane];
        s += v.x * v.x + v.y * v.y + v.z * v.z + v.w * v.w;
    }
#pragma unroll
    for (int off = 16; off; off >>= 1)
        s += __shfl_xor_sync(0xffffffffu, s, off);
    if (lane == 0) g_half_e2[c] = 0.5f * s;
}

// ---------------------------------------------------------------------------
// Fused GEMM + argmax + gather.
// Block: 128 tokens x (all 8192 codes, 128 at a time). 256 threads, 8x8/thread.
// score[t][c] = dot(x[t], e[c]) - 0.5*||e[c]||^2 ; argmax (ties -> lowest c).
// ---------------------------------------------------------------------------
__global__ __launch_bounds__(256, 2)
void vq_kernel(const float* __restrict__ x,
               const int* __restrict__ ilen,
               const float* __restrict__ embed,
               float* __restrict__ outq,
               float* __restrict__ outi) {
    __shared__ float sX[2][8][132];   // +4 pad: conflict-free STS
    __shared__ float sE[2][8][132];
    __shared__ float sHE[128];
    __shared__ int   sBI[128];

    const int tid = threadIdx.x;
    const int m0 = blockIdx.x * 128;          // first token of this block
    const int b = m0 / SS;
    const int sbase = m0 % SS;                // 128 | SS, so one batch row per block
    const int len = ilen[b];

    if (sbase >= len) {
        // fully masked tile: zeros + (-1)
        float4 z = make_float4(0.f, 0.f, 0.f, 0.f);
        float4* oq = (float4*)outq;
        for (int i = tid; i < 128 * (DD / 4); i += 256)
            oq[(size_t)m0 * (DD / 4) + i] = z;
        if (outi && tid < 128) outi[m0 + tid] = -1.0f;
        return;
    }

    const int row = tid >> 1;                 // 0..127 (token / code row loaded)
    const int seg = tid & 1;                  // which half of the 8-wide k chunk
    const int tm = (tid >> 4) * 8;            // token sub-tile base
    const int tn = (tid & 15) * 8;            // code sub-tile base

    float runBest[8];
    int   runIdx[8];
#pragma unroll
    for (int i = 0; i < 8; i++) { runBest[i] = -3.402823466e38f; runIdx[i] = 0; }

    const size_t xrow = (size_t)(m0 + row) * DD;

    for (int ct = 0; ct < CC / 128; ct++) {
        const int c0 = ct * 128;
        if (tid < 128) sHE[tid] = g_half_e2[c0 + tid];

        float acc[8][8];
#pragma unroll
        for (int i = 0; i < 8; i++)
#pragma unroll
            for (int j = 0; j < 8; j++) acc[i][j] = 0.f;

        const size_t erow = (size_t)(c0 + row) * DD;

        // prologue: chunk 0 -> buffer 0
        {
            float4 xr = *(const float4*)&x[xrow + seg * 4];
            float4 er = *(const float4*)&embed[erow + seg * 4];
            int kb = seg * 4;
            sX[0][kb + 0][row] = xr.x; sX[0][kb + 1][row] = xr.y;
            sX[0][kb + 2][row] = xr.z; sX[0][kb + 3][row] = xr.w;
            sE[0][kb + 0][row] = er.x; sE[0][kb + 1][row] = er.y;
            sE[0][kb + 2][row] = er.z; sE[0][kb + 3][row] = er.w;
        }
        __syncthreads();

        for (int kt = 0; kt < DD / 8; kt++) {
            const int cur = kt & 1;
            float4 xn, en;
            if (kt < DD / 8 - 1) {
                xn = *(const float4*)&x[xrow + (kt + 1) * 8 + seg * 4];
                en = *(const float4*)&embed[erow + (kt + 1) * 8 + seg * 4];
            }
#pragma unroll
            for (int k = 0; k < 8; k++) {
                float4 a0 = *(const float4*)&sX[cur][k][tm];
                float4 a1 = *(const float4*)&sX[cur][k][tm + 4];
                float4 b0 = *(const float4*)&sE[cur][k][tn];
                float4 b1 = *(const float4*)&sE[cur][k][tn + 4];
                float av[8] = {a0.x, a0.y, a0.z, a0.w, a1.x, a1.y, a1.z, a1.w};
                float bv[8] = {b0.x, b0.y, b0.z, b0.w, b1.x, b1.y, b1.z, b1.w};
#pragma unroll
                for (int i = 0; i < 8; i++)
#pragma unroll
                    for (int j = 0; j < 8; j++)
                        acc[i][j] = fmaf(av[i], bv[j], acc[i][j]);
            }
            if (kt < DD / 8 - 1) {
                int nb = cur ^ 1, kb = seg * 4;
                sX[nb][kb + 0][row] = xn.x; sX[nb][kb + 1][row] = xn.y;
                sX[nb][kb + 2][row] = xn.z; sX[nb][kb + 3][row] = xn.w;
                sE[nb][kb + 0][row] = en.x; sE[nb][kb + 1][row] = en.y;
                sE[nb][kb + 2][row] = en.z; sE[nb][kb + 3][row] = en.w;
            }
            __syncthreads();
        }

        // epilogue: per-token argmax over this 128-code tile, then running update
#pragma unroll
        for (int i = 0; i < 8; i++) {
            float best = acc[i][0] - sHE[tn + 0];
            int idx = c0 + tn;
#pragma unroll
            for (int j = 1; j < 8; j++) {
                float v = acc[i][j] - sHE[tn + j];
                if (v > best) { best = v; idx = c0 + tn + j; }
            }
            // butterfly over the 16 lanes sharing these 8 tokens
#pragma unroll
            for (int off = 8; off; off >>= 1) {
                float ov = __shfl_xor_sync(0xffffffffu, best, off);
                int   oi = __shfl_xor_sync(0xffffffffu, idx, off);
                if (ov > best || (ov == best && oi < idx)) { best = ov; idx = oi; }
            }
            // strict > keeps earlier (lower) code tile on ties -> jnp.argmax semantics
            if (best > runBest[i]) { runBest[i] = best; runIdx[i] = idx; }
        }
        __syncthreads();   // protect sHE / smem for next tile
    }

    if ((tid & 15) == 0) {
#pragma unroll
        for (int i = 0; i < 8; i++) sBI[tm + i] = runIdx[i];
    }
    __syncthreads();

    // gather + masked write
    const float4* e4 = (const float4*)embed;
    float4* oq = (float4*)outq;
    for (int t = tid; t < 128 * (DD / 4); t += 256) {
        int m = t >> 7;           // DD/4 == 128
        int d4 = t & 127;
        bool act = (sbase + m) < len;
        float4 v = make_float4(0.f, 0.f, 0.f, 0.f);
        if (act) v = e4[(size_t)sBI[m] * (DD / 4) + d4];
        oq[(size_t)(m0 + m) * (DD / 4) + d4] = v;
    }
    if (outi && tid < 128) {
        bool act = (sbase + tid) < len;
        outi[m0 + tid] = act ? (float)sBI[tid] : -1.0f;
    }
}

// ---------------------------------------------------------------------------
// Launch
// ---------------------------------------------------------------------------
extern "C" void kernel_launch(void* const* d_in, const int* in_sizes, int n_in,
                              void* d_out, int out_size) {
    const float* xp = nullptr;
    const int* lp = nullptr;
    const float* ep = nullptr;
    for (int i = 0; i < n_in; i++) {
        if (in_sizes[i] == MM * DD)      xp = (const float*)d_in[i];
        else if (in_sizes[i] == CC * DD) ep = (const float*)d_in[i];
        else if (in_sizes[i] == BB)      lp = (const int*)d_in[i];
    }
    float* oq = (float*)d_out;
    float* oi = (out_size >= (int)((size_t)MM * DD + MM)) ? oq + (size_t)MM * DD
                                                          : nullptr;

    half_e2_kernel<<<CC / 8, 256>>>(ep);
    vq_kernel<<<MM / 128, 256>>>(xp, lp, ep, oq, oi);
}

// round 7
// speedup vs baseline: 8.5887x; 8.5887x over previous
#include <cuda_runtime.h>
#include <cuda_bf16.h>
#include <cstdint>

#define BB 16
#define SS 2048
#define DD 512
#define CC 8192
#define MM (BB*SS)

#define SPLITS 4
#define CPS (CC/SPLITS)          // 2048 codes per split
#define NTILES (CPS/128)         // 16 code tiles per split
#define TOTCH (NTILES*8)         // 128 K-chunks (64 wide) per CTA
#define CAND 32
#define TAU 0.09375f
#define RMINIT 1.5f

// ---------------- scratch (aligned: cp.async needs 16B-aligned gmem) ---------
__device__ __align__(128) float          g_half_e2[CC];
__device__ __align__(128) __nv_bfloat16  g_ebf[(size_t)CC * DD];   // 8 MB
__device__ __align__(128) __nv_bfloat16  g_xbf[(size_t)MM * DD];   // 32 MB
__device__ __align__(128) int            g_cand[(size_t)MM * SPLITS * CAND];
__device__ __align__(128) int            g_cnt[(size_t)MM * SPLITS];

// ---------------- helpers ----------------------------------------------------
__device__ __forceinline__ uint32_t smem_u32(const void* p) {
    uint32_t a;
    asm("{ .reg .u64 t; cvta.to.shared.u64 t, %1; cvt.u32.u64 %0, t; }"
        : "=r"(a) : "l"(p));
    return a;
}

#define CP_ASYNC16(dst, src) \
    asm volatile("cp.async.cg.shared.global [%0], [%1], 16;" \
                 :: "r"(dst), "l"(__cvta_generic_to_global(src)) : "memory")
#define CP_COMMIT  asm volatile("cp.async.commit_group;" ::: "memory")
#define CP_WAIT(n) asm volatile("cp.async.wait_group %0;" :: "n"(n) : "memory")

#define LDSM4(r, addr) \
    asm volatile("ldmatrix.sync.aligned.m8n8.x4.shared.b16 {%0,%1,%2,%3}, [%4];" \
                 : "=r"((r)[0]), "=r"((r)[1]), "=r"((r)[2]), "=r"((r)[3]) : "r"(addr))

#define MMA16816(d, a, b0, b1) \
    asm volatile("mma.sync.aligned.m16n8k16.row.col.f32.bf16.bf16.f32 " \
                 "{%0,%1,%2,%3}, {%4,%5,%6,%7}, {%8,%9}, {%0,%1,%2,%3};" \
                 : "+f"((d)[0]), "+f"((d)[1]), "+f"((d)[2]), "+f"((d)[3]) \
                 : "r"((a)[0]), "r"((a)[1]), "r"((a)[2]), "r"((a)[3]), \
                   "r"(b0), "r"(b1))

// ---------------- prep kernels ----------------------------------------------
__global__ void prep_embed(const float* __restrict__ embed) {
    int c = blockIdx.x * 8 + (threadIdx.x >> 5);
    int lane = threadIdx.x & 31;
    const float4* e4 = (const float4*)embed;
    uint2* eb = (uint2*)g_ebf;
    float s = 0.f;
#pragma unroll
    for (int j = 0; j < 4; j++) {
        float4 v = e4[(size_t)c * (DD / 4) + j * 32 + lane];
        s += v.x * v.x + v.y * v.y + v.z * v.z + v.w * v.w;
        __nv_bfloat162 p0 = __floats2bfloat162_rn(v.x, v.y);
        __nv_bfloat162 p1 = __floats2bfloat162_rn(v.z, v.w);
        uint2 u;
        u.x = *reinterpret_cast<uint32_t*>(&p0);
        u.y = *reinterpret_cast<uint32_t*>(&p1);
        eb[(size_t)c * (DD / 4) + j * 32 + lane] = u;
    }
#pragma unroll
    for (int off = 16; off; off >>= 1) s += __shfl_xor_sync(0xffffffffu, s, off);
    if (lane == 0) g_half_e2[c] = 0.5f * s;

    int gid = blockIdx.x * 256 + threadIdx.x;
    if (gid < MM * SPLITS) g_cnt[gid] = 0;
}

__global__ void prep_x(const float* __restrict__ x) {
    int t = blockIdx.x * 8 + (threadIdx.x >> 5);
    int lane = threadIdx.x & 31;
    const float4* x4 = (const float4*)x;
    uint2* xb = (uint2*)g_xbf;
#pragma unroll
    for (int j = 0; j < 4; j++) {
        float4 v = x4[(size_t)t * (DD / 4) + j * 32 + lane];
        __nv_bfloat162 p0 = __floats2bfloat162_rn(v.x, v.y);
        __nv_bfloat162 p1 = __floats2bfloat162_rn(v.z, v.w);
        uint2 u;
        u.x = *reinterpret_cast<uint32_t*>(&p0);
        u.y = *reinterpret_cast<uint32_t*>(&p1);
        xb[(size_t)t * (DD / 4) + j * 32 + lane] = u;
    }
}

// ---------------- HMMA candidate pass ----------------------------------------
// grid (256, 4). CTA: 128 tokens x 2048-code split. 8 warps, warp tile 32x64.
#define SMEM_A   131072
#define SMEM_BCH 16384
#define SMEM_DYN (SMEM_A + 4 * SMEM_BCH)

__global__ __launch_bounds__(256, 1)
void vq_gemm(const int* __restrict__ ilen) {
    extern __shared__ char dsm[];
    __shared__ float sHE[128];

    const int tid = threadIdx.x, lane = tid & 31, wid = tid >> 5;
    const int m0 = blockIdx.x * 128;
    if ((m0 & (SS - 1)) >= ilen[m0 >> 11]) return;   // fully masked tile
    const int split = blockIdx.y;
    const int split0 = split * CPS;

    const uint32_t sA = smem_u32(dsm);
    const uint32_t sB = sA + SMEM_A;

    {   // A prefetch (in group 0 together with B chunk 0)
        const __nv_bfloat16* xb = g_xbf + (size_t)m0 * DD;
        for (int i = tid; i < 8192; i += 256) {
            int row = i >> 6, g = i & 63;
            uint32_t dst = sA + row * 1024 + ((g ^ (row & 7)) << 4);
            CP_ASYNC16(dst, xb + (size_t)row * DD + g * 8);
        }
    }
    auto prefB = [&](int gi) {
        const __nv_bfloat16* src0 =
            g_ebf + (size_t)(split0 + (gi >> 3) * 128) * DD + (gi & 7) * 64;
        uint32_t bb = sB + (gi & 3) * SMEM_BCH;
        for (int i = tid; i < 1024; i += 256) {
            int row = i >> 3, g = i & 7;
            uint32_t dst = bb + row * 128 + ((g ^ (row & 7)) << 4);
            CP_ASYNC16(dst, src0 + (size_t)row * DD + g * 8);
        }
    };
    prefB(0); CP_COMMIT;
    prefB(1); CP_COMMIT;
    prefB(2); CP_COMMIT;

    const int wm = wid >> 1, wn = wid & 1;
    const int rA0 = wm * 32 + (lane & 15);
    const int kgA_off = lane >> 4;
    const int rB0 = wn * 64 + (lane & 7) + ((lane >> 4) << 3);
    const int kgB_off = (lane >> 3) & 1;

    float acc[2][8][4];
    float runmax[2][2] = {{RMINIT, RMINIT}, {RMINIT, RMINIT}};

    for (int gi = 0; gi < TOTCH; gi++) {
        const int nt = gi >> 3, ck = gi & 7;
        if (gi < TOTCH - 2)       CP_WAIT(2);
        else if (gi == TOTCH - 2) CP_WAIT(1);
        else                      CP_WAIT(0);
        __syncthreads();
        if (gi + 3 < TOTCH) { prefB(gi + 3); CP_COMMIT; }

        if (ck == 0) {
            if (tid < 128) sHE[tid] = g_half_e2[split0 + nt * 128 + tid];
#pragma unroll
            for (int mt = 0; mt < 2; mt++)
#pragma unroll
                for (int j = 0; j < 8; j++)
#pragma unroll
                    for (int q = 0; q < 4; q++) acc[mt][j][q] = 0.f;
        }

        const uint32_t bb = sB + (gi & 3) * SMEM_BCH;
#pragma unroll
        for (int ks = 0; ks < 4; ks++) {
            uint32_t a[2][4], b[4][4];
            const int kgA = ck * 8 + ks * 2 + kgA_off;
#pragma unroll
            for (int mt = 0; mt < 2; mt++) {
                int row = rA0 + mt * 16;
                LDSM4(a[mt], sA + row * 1024 + ((kgA ^ (row & 7)) << 4));
            }
            const int kgB = ks * 2 + kgB_off;
#pragma unroll
            for (int np = 0; np < 4; np++) {
                int row = rB0 + np * 16;
                LDSM4(b[np], bb + row * 128 + ((kgB ^ (row & 7)) << 4));
            }
#pragma unroll
            for (int mt = 0; mt < 2; mt++)
#pragma unroll
                for (int np = 0; np < 4; np++) {
                    MMA16816(acc[mt][np * 2],     a[mt], b[np][0], b[np][1]);
                    MMA16816(acc[mt][np * 2 + 1], a[mt], b[np][2], b[np][3]);
                }
        }

        if (ck == 7) {   // epilogue for this 128-code tile
            float sh[16];
#pragma unroll
            for (int n8 = 0; n8 < 8; n8++) {
                sh[n8 * 2]     = sHE[wn * 64 + n8 * 8 + (lane & 3) * 2];
                sh[n8 * 2 + 1] = sHE[wn * 64 + n8 * 8 + (lane & 3) * 2 + 1];
            }
            const int c0 = split0 + nt * 128;
#pragma unroll
            for (int mt = 0; mt < 2; mt++)
#pragma unroll
                for (int hh = 0; hh < 2; hh++) {
                    float s[16];
#pragma unroll
                    for (int n8 = 0; n8 < 8; n8++) {
                        s[n8 * 2]     = acc[mt][n8][hh * 2]     - sh[n8 * 2];
                        s[n8 * 2 + 1] = acc[mt][n8][hh * 2 + 1] - sh[n8 * 2 + 1];
                    }
                    float m = s[0];
#pragma unroll
                    for (int j = 1; j < 16; j++) m = fmaxf(m, s[j]);
                    m = fmaxf(m, __shfl_xor_sync(0xffffffffu, m, 1));
                    m = fmaxf(m, __shfl_xor_sync(0xffffffffu, m, 2));
                    float rm = fmaxf(runmax[mt][hh], m);
                    runmax[mt][hh] = rm;
                    const float thr = rm - TAU;
                    const int row = m0 + wm * 32 + mt * 16 + hh * 8 + (lane >> 2);
#pragma unroll
                    for (int j = 0; j < 16; j++) {
                        if (s[j] >= thr) {
                            int pos = atomicAdd(&g_cnt[(size_t)row * SPLITS + split], 1);
                            if (pos < CAND)
                                g_cand[((size_t)row * SPLITS + split) * CAND + pos] =
                                    c0 + wn * 64 + (j >> 1) * 8 + (lane & 3) * 2 + (j & 1);
                        }
                    }
                }
        }
    }
}

// ---------------- exact fp32 rescore + gather --------------------------------
__global__ __launch_bounds__(256)
void vq_rescore(const float* __restrict__ x, const int* __restrict__ ilen,
                const float* __restrict__ embed,
                float* __restrict__ outq, float* __restrict__ outi) {
    const int wid = threadIdx.x >> 5, lane = threadIdx.x & 31;
    const int t = blockIdx.x * 8 + wid;
    const int s = t & (SS - 1);
    const int len = ilen[t >> 11];
    float4* oq = (float4*)outq;

    if (s >= len) {
        float4 z = make_float4(0.f, 0.f, 0.f, 0.f);
#pragma unroll
        for (int j = 0; j < 4; j++) oq[(size_t)t * (DD / 4) + j * 32 + lane] = z;
        if (outi && lane == 0) outi[t] = -1.0f;
        return;
    }

    const float4* x4 = (const float4*)x;
    const float4* e4 = (const float4*)embed;
    float4 xr[4];
#pragma unroll
    for (int j = 0; j < 4; j++) xr[j] = x4[(size_t)t * (DD / 4) + j * 32 + lane];

    float best = -3.402823466e38f;
    int bi = 0;
    for (int sp = 0; sp < SPLITS; sp++) {
        int cn = g_cnt[(size_t)t * SPLITS + sp];
        if (cn > CAND) cn = CAND;
        for (int k = 0; k < cn; k++) {
            int idx = g_cand[((size_t)t * SPLITS + sp) * CAND + k];
            float acc = 0.f;
#pragma unroll
            for (int j = 0; j < 4; j++) {
                float4 e = e4[(size_t)idx * (DD / 4) + j * 32 + lane];
                acc += xr[j].x * e.x + xr[j].y * e.y + xr[j].z * e.z + xr[j].w * e.w;
            }
#pragma unroll
            for (int off = 16; off; off >>= 1)
                acc += __shfl_xor_sync(0xffffffffu, acc, off);
            float sc = acc - g_half_e2[idx];
            if (sc > best || (sc == best && idx < bi)) { best = sc; bi = idx; }
        }
    }
#pragma unroll
    for (int j = 0; j < 4; j++)
        oq[(size_t)t * (DD / 4) + j * 32 + lane] = e4[(size_t)bi * (DD / 4) + j * 32 + lane];
    if (outi && lane == 0) outi[t] = (float)bi;
}

// ---------------- launch ------------------------------------------------------
extern "C" void kernel_launch(void* const* d_in, const int* in_sizes, int n_in,
                              void* d_out, int out_size) {
    const float* xp = nullptr;
    const int* lp = nullptr;
    const float* ep = nullptr;
    for (int i = 0; i < n_in; i++) {
        if (in_sizes[i] == MM * DD)      xp = (const float*)d_in[i];
        else if (in_sizes[i] == CC * DD) ep = (const float*)d_in[i];
        else if (in_sizes[i] == BB)      lp = (const int*)d_in[i];
    }
    float* oq = (float*)d_out;
    float* oi = (out_size >= (int)((size_t)MM * DD + MM)) ? oq + (size_t)MM * DD : nullptr;

    cudaFuncSetAttribute(vq_gemm, cudaFuncAttributeMaxDynamicSharedMemorySize, SMEM_DYN);

    prep_embed<<<CC / 8, 256>>>(ep);
    prep_x<<<MM / 8, 256>>>(xp);
    vq_gemm<<<dim3(256, SPLITS), 256, SMEM_DYN>>>(lp);
    vq_rescore<<<MM / 8, 256>>>(xp, lp, ep, oq, oi);
}

// round 9
// speedup vs baseline: 9.8584x; 1.1478x over previous
#include <cuda_runtime.h>
#include <cuda_bf16.h>
#include <cstdint>

#define BB 16
#define SS 2048
#define DD 512
#define CC 8192
#define MM (BB*SS)

#define SPLITS 4
#define CPS (CC/SPLITS)          // 2048 codes per split
#define NTILE 256                // codes per tile (B chunk width)
#define NTILES (CPS/NTILE)       // 8 tiles per split
#define TOTCH (NTILES*8)         // 64 K-chunks per CTA
#define CAND 32
#define TAU 0.09375f
#define RMINIT 1.5f

// ---------------- scratch (16B-aligned for cp.async) -------------------------
__device__ __align__(128) float          g_half_e2[CC];
__device__ __align__(128) __nv_bfloat16  g_ebf[(size_t)CC * DD];   // 8 MB
__device__ __align__(128) __nv_bfloat16  g_xbf[(size_t)MM * DD];   // 32 MB
__device__ __align__(128) int            g_cand[(size_t)MM * SPLITS * CAND];
__device__ __align__(128) int            g_cnt[(size_t)MM * SPLITS];

// ---------------- helpers ----------------------------------------------------
__device__ __forceinline__ uint32_t smem_u32(const void* p) {
    uint32_t a;
    asm("{ .reg .u64 t; cvta.to.shared.u64 t, %1; cvt.u32.u64 %0, t; }"
        : "=r"(a) : "l"(p));
    return a;
}

#define CP_ASYNC16(dst, src) \
    asm volatile("cp.async.cg.shared.global [%0], [%1], 16;" \
                 :: "r"(dst), "l"(__cvta_generic_to_global(src)) : "memory")
#define CP_COMMIT  asm volatile("cp.async.commit_group;" ::: "memory")
#define CP_WAIT(n) asm volatile("cp.async.wait_group %0;" :: "n"(n) : "memory")

#define LDSM4(r, addr) \
    asm volatile("ldmatrix.sync.aligned.m8n8.x4.shared.b16 {%0,%1,%2,%3}, [%4];" \
                 : "=r"((r)[0]), "=r"((r)[1]), "=r"((r)[2]), "=r"((r)[3]) : "r"(addr))

#define MMA16816(d, a, b0, b1) \
    asm volatile("mma.sync.aligned.m16n8k16.row.col.f32.bf16.bf16.f32 " \
                 "{%0,%1,%2,%3}, {%4,%5,%6,%7}, {%8,%9}, {%0,%1,%2,%3};" \
                 : "+f"((d)[0]), "+f"((d)[1]), "+f"((d)[2]), "+f"((d)[3]) \
                 : "r"((a)[0]), "r"((a)[1]), "r"((a)[2]), "r"((a)[3]), \
                   "r"(b0), "r"(b1))

// ---------------- prep kernels ------------------------------------------------
__global__ void prep_embed(const float* __restrict__ embed) {
    int c = blockIdx.x * 8 + (threadIdx.x >> 5);
    int lane = threadIdx.x & 31;
    const float4* e4 = (const float4*)embed;
    uint2* eb = (uint2*)g_ebf;
    float s = 0.f;
#pragma unroll
    for (int j = 0; j < 4; j++) {
        float4 v = e4[(size_t)c * (DD / 4) + j * 32 + lane];
        s += v.x * v.x + v.y * v.y + v.z * v.z + v.w * v.w;
        __nv_bfloat162 p0 = __floats2bfloat162_rn(v.x, v.y);
        __nv_bfloat162 p1 = __floats2bfloat162_rn(v.z, v.w);
        uint2 u;
        u.x = *reinterpret_cast<uint32_t*>(&p0);
        u.y = *reinterpret_cast<uint32_t*>(&p1);
        eb[(size_t)c * (DD / 4) + j * 32 + lane] = u;
    }
#pragma unroll
    for (int off = 16; off; off >>= 1) s += __shfl_xor_sync(0xffffffffu, s, off);
    if (lane == 0) g_half_e2[c] = 0.5f * s;

    int gid = blockIdx.x * 256 + threadIdx.x;
    if (gid < MM * SPLITS) g_cnt[gid] = 0;
}

__global__ void prep_x(const float* __restrict__ x) {
    int t = blockIdx.x * 8 + (threadIdx.x >> 5);
    int lane = threadIdx.x & 31;
    const float4* x4 = (const float4*)x;
    uint2* xb = (uint2*)g_xbf;
#pragma unroll
    for (int j = 0; j < 4; j++) {
        float4 v = x4[(size_t)t * (DD / 4) + j * 32 + lane];
        __nv_bfloat162 p0 = __floats2bfloat162_rn(v.x, v.y);
        __nv_bfloat162 p1 = __floats2bfloat162_rn(v.z, v.w);
        uint2 u;
        u.x = *reinterpret_cast<uint32_t*>(&p0);
        u.y = *reinterpret_cast<uint32_t*>(&p1);
        xb[(size_t)t * (DD / 4) + j * 32 + lane] = u;
    }
}

// ---------------- HMMA candidate pass -----------------------------------------
// grid (256, 4). CTA: 128 tokens x 2048-code split. 16 warps, warp tile 32x64,
// CTA tile per chunk = 128 x 256. A resident (128KB), B 3-stage 32KB chunks.
#define SMEM_A   131072
#define SMEM_BCH 32768
#define SMEM_DYN (SMEM_A + 3 * SMEM_BCH)

__global__ __launch_bounds__(512, 1)
void vq_gemm(const int* __restrict__ ilen) {
    extern __shared__ char dsm[];
    __shared__ float sHE[NTILE];

    const int tid = threadIdx.x, lane = tid & 31, wid = tid >> 5;
    const int m0 = blockIdx.x * 128;
    if ((m0 & (SS - 1)) >= ilen[m0 >> 11]) return;   // fully masked tile
    const int split = blockIdx.y;
    const int split0 = split * CPS;

    const uint32_t sA = smem_u32(dsm);
    const uint32_t sB = sA + SMEM_A;

    {   // A prefetch: 128 tokens x 512 k, swizzled rows of 1KB
        const __nv_bfloat16* xb = g_xbf + (size_t)m0 * DD;
        for (int i = tid; i < 8192; i += 512) {
            int row = i >> 6, g = i & 63;
            uint32_t dst = sA + row * 1024 + ((g ^ (row & 7)) << 4);
            CP_ASYNC16(dst, xb + (size_t)row * DD + g * 8);
        }
    }
    auto prefB = [&](int gi) {   // 256 codes x 64 k = 32 KB
        const __nv_bfloat16* src0 =
            g_ebf + (size_t)(split0 + (gi >> 3) * NTILE) * DD + (gi & 7) * 64;
        uint32_t bb = sB + (gi % 3) * SMEM_BCH;
        for (int i = tid; i < 2048; i += 512) {
            int row = i >> 3, g = i & 7;
            uint32_t dst = bb + row * 128 + ((g ^ (row & 7)) << 4);
            CP_ASYNC16(dst, src0 + (size_t)row * DD + g * 8);
        }
    };
    prefB(0); CP_COMMIT;     // group 0: A + B0
    prefB(1); CP_COMMIT;     // group 1: B1

    const int wm = wid >> 2, wn = wid & 3;                 // 4 x 4 warp grid
    const int rA0 = wm * 32 + (lane & 15);
    const int kgA_off = lane >> 4;
    const int rB0 = wn * 64 + (lane & 7) + ((lane >> 4) << 3);
    const int kgB_off = (lane >> 3) & 1;

    float acc[2][8][4];
    float runmax[2][2] = {{RMINIT, RMINIT}, {RMINIT, RMINIT}};

    for (int gi = 0; gi < TOTCH; gi++) {
        const int nt = gi >> 3, ck = gi & 7;
        if (gi < TOTCH - 1) CP_WAIT(1); else CP_WAIT(0);
        __syncthreads();
        if (gi + 2 < TOTCH) { prefB(gi + 2); CP_COMMIT; }

        if (ck == 0) {
            if (tid < NTILE) sHE[tid] = g_half_e2[split0 + nt * NTILE + tid];
#pragma unroll
            for (int mt = 0; mt < 2; mt++)
#pragma unroll
                for (int j = 0; j < 8; j++)
#pragma unroll
                    for (int q = 0; q < 4; q++) acc[mt][j][q] = 0.f;
        }

        const uint32_t bb = sB + (gi % 3) * SMEM_BCH;
#pragma unroll
        for (int ks = 0; ks < 4; ks++) {
            uint32_t a[2][4], b[4][4];
            const int kgA = ck * 8 + ks * 2 + kgA_off;
#pragma unroll
            for (int mt = 0; mt < 2; mt++) {
                int row = rA0 + mt * 16;
                LDSM4(a[mt], sA + row * 1024 + ((kgA ^ (row & 7)) << 4));
            }
            const int kgB = ks * 2 + kgB_off;
#pragma unroll
            for (int np = 0; np < 4; np++) {
                int row = rB0 + np * 16;
                LDSM4(b[np], bb + row * 128 + ((kgB ^ (row & 7)) << 4));
            }
#pragma unroll
            for (int mt = 0; mt < 2; mt++)
#pragma unroll
                for (int np = 0; np < 4; np++) {
                    MMA16816(acc[mt][np * 2],     a[mt], b[np][0], b[np][1]);
                    MMA16816(acc[mt][np * 2 + 1], a[mt], b[np][2], b[np][3]);
                }
        }

        if (ck == 7) {   // epilogue for this 256-code tile
            float sh[16];
#pragma unroll
            for (int n8 = 0; n8 < 8; n8++) {
                sh[n8 * 2]     = sHE[wn * 64 + n8 * 8 + (lane & 3) * 2];
                sh[n8 * 2 + 1] = sHE[wn * 64 + n8 * 8 + (lane & 3) * 2 + 1];
            }
            const int c0 = split0 + nt * NTILE;
#pragma unroll
            for (int mt = 0; mt < 2; mt++)
#pragma unroll
                for (int hh = 0; hh < 2; hh++) {
                    float s[16];
#pragma unroll
                    for (int n8 = 0; n8 < 8; n8++) {
                        s[n8 * 2]     = acc[mt][n8][hh * 2]     - sh[n8 * 2];
                        s[n8 * 2 + 1] = acc[mt][n8][hh * 2 + 1] - sh[n8 * 2 + 1];
                    }
                    float m = s[0];
#pragma unroll
                    for (int j = 1; j < 16; j++) m = fmaxf(m, s[j]);
                    m = fmaxf(m, __shfl_xor_sync(0xffffffffu, m, 1));
                    m = fmaxf(m, __shfl_xor_sync(0xffffffffu, m, 2));
                    float rm = fmaxf(runmax[mt][hh], m);
                    runmax[mt][hh] = rm;
                    const float thr = rm - TAU;
                    const int row = m0 + wm * 32 + mt * 16 + hh * 8 + (lane >> 2);
#pragma unroll
                    for (int j = 0; j < 16; j++) {
                        if (s[j] >= thr) {
                            int pos = atomicAdd(&g_cnt[(size_t)row * SPLITS + split], 1);
                            if (pos < CAND)
                                g_cand[((size_t)row * SPLITS + split) * CAND + pos] =
                                    c0 + wn * 64 + (j >> 1) * 8 + (lane & 3) * 2 + (j & 1);
                        }
                    }
                }
        }
    }
}

// ---------------- exact fp32 rescore + gather ----------------------------------
__global__ __launch_bounds__(256)
void vq_rescore(const float* __restrict__ x, const int* __restrict__ ilen,
                const float* __restrict__ embed,
                float* __restrict__ outq, float* __restrict__ outi) {
    const int wid = threadIdx.x >> 5, lane = threadIdx.x & 31;
    const int t = blockIdx.x * 8 + wid;
    const int s = t & (SS - 1);
    const int len = ilen[t >> 11];
    float4* oq = (float4*)outq;

    if (s >= len) {
        float4 z = make_float4(0.f, 0.f, 0.f, 0.f);
#pragma unroll
        for (int j = 0; j < 4; j++) oq[(size_t)t * (DD / 4) + j * 32 + lane] = z;
        if (outi && lane == 0) outi[t] = -1.0f;
        return;
    }

    const float4* x4 = (const float4*)x;
    const float4* e4 = (const float4*)embed;
    float4 xr[4];
#pragma unroll
    for (int j = 0; j < 4; j++) xr[j] = x4[(size_t)t * (DD / 4) + j * 32 + lane];

    float best = -3.402823466e38f;
    int bi = 0;
    for (int sp = 0; sp < SPLITS; sp++) {
        int cn = g_cnt[(size_t)t * SPLITS + sp];
        if (cn > CAND) cn = CAND;
        for (int k = 0; k < cn; k++) {
            int idx = g_cand[((size_t)t * SPLITS + sp) * CAND + k];
            float acc = 0.f;
#pragma unroll
            for (int j = 0; j < 4; j++) {
                float4 e = e4[(size_t)idx * (DD / 4) + j * 32 + lane];
                acc += xr[j].x * e.x + xr[j].y * e.y + xr[j].z * e.z + xr[j].w * e.w;
            }
#pragma unroll
            for (int off = 16; off; off >>= 1)
                acc += __shfl_xor_sync(0xffffffffu, acc, off);
            float sc = acc - g_half_e2[idx];
            if (sc > best || (sc == best && idx < bi)) { best = sc; bi = idx; }
        }
    }
#pragma unroll
    for (int j = 0; j < 4; j++)
        oq[(size_t)t * (DD / 4) + j * 32 + lane] = e4[(size_t)bi * (DD / 4) + j * 32 + lane];
    if (outi && lane == 0) outi[t] = (float)bi;
}

// ---------------- launch --------------------------------------------------------
extern "C" void kernel_launch(void* const* d_in, const int* in_sizes, int n_in,
                              void* d_out, int out_size) {
    const float* xp = nullptr;
    const int* lp = nullptr;
    const float* ep = nullptr;
    for (int i = 0; i < n_in; i++) {
        if (in_sizes[i] == MM * DD)      xp = (const float*)d_in[i];
        else if (in_sizes[i] == CC * DD) ep = (const float*)d_in[i];
        else if (in_sizes[i] == BB)      lp = (const int*)d_in[i];
    }
    float* oq = (float*)d_out;
    float* oi = (out_size >= (int)((size_t)MM * DD + MM)) ? oq + (size_t)MM * DD : nullptr;

    cudaFuncSetAttribute(vq_gemm, cudaFuncAttributeMaxDynamicSharedMemorySize, SMEM_DYN);

    prep_embed<<<CC / 8, 256>>>(ep);
    prep_x<<<MM / 8, 256>>>(xp);
    vq_gemm<<<dim3(256, SPLITS), 512, SMEM_DYN>>>(lp);
    vq_rescore<<<MM / 8, 256>>>(xp, lp, ep, oq, oi);
}

// round 11
// speedup vs baseline: 9.8733x; 1.0015x over previous
#include <cuda_runtime.h>
#include <cuda_bf16.h>
#include <cstdint>

#define BB 16
#define SS 2048
#define DD 512
#define CC 8192
#define MM (BB*SS)

#define SPLITS 4
#define CPS (CC/SPLITS)          // 2048 codes per split
#define NTILE 256                // codes per tile (B chunk width)
#define NTILES (CPS/NTILE)       // 8 tiles per split
#define TOTCH (NTILES*8)         // 64 K-chunks per CTA
#define CAND 32
#define TAU 0.09375f
#define RMINIT 1.5f

// ---------------- scratch (16B-aligned for cp.async) -------------------------
__device__ __align__(128) float          g_half_e2[CC];
__device__ __align__(128) __nv_bfloat16  g_ebf[(size_t)CC * DD];   // 8 MB
__device__ __align__(128) __nv_bfloat16  g_xbf[(size_t)MM * DD];   // 32 MB
__device__ __align__(128) int            g_cand[(size_t)MM * SPLITS * CAND];
__device__ __align__(128) int            g_cnt[(size_t)MM * SPLITS];

// ---------------- helpers ----------------------------------------------------
__device__ __forceinline__ uint32_t smem_u32(const void* p) {
    uint32_t a;
    asm("{ .reg .u64 t; cvta.to.shared.u64 t, %1; cvt.u32.u64 %0, t; }"
        : "=r"(a) : "l"(p));
    return a;
}

#define CP_ASYNC16(dst, src) \
    asm volatile("cp.async.cg.shared.global [%0], [%1], 16;" \
                 :: "r"(dst), "l"(__cvta_generic_to_global(src)) : "memory")
#define CP_COMMIT  asm volatile("cp.async.commit_group;" ::: "memory")
#define CP_WAIT(n) asm volatile("cp.async.wait_group %0;" :: "n"(n) : "memory")

#define LDSM4(r, addr) \
    asm volatile("ldmatrix.sync.aligned.m8n8.x4.shared.b16 {%0,%1,%2,%3}, [%4];" \
                 : "=r"((r)[0]), "=r"((r)[1]), "=r"((r)[2]), "=r"((r)[3]) : "r"(addr))

#define MMA16816(d, a, b0, b1) \
    asm volatile("mma.sync.aligned.m16n8k16.row.col.f32.bf16.bf16.f32 " \
                 "{%0,%1,%2,%3}, {%4,%5,%6,%7}, {%8,%9}, {%0,%1,%2,%3};" \
                 : "+f"((d)[0]), "+f"((d)[1]), "+f"((d)[2]), "+f"((d)[3]) \
                 : "r"((a)[0]), "r"((a)[1]), "r"((a)[2]), "r"((a)[3]), \
                   "r"(b0), "r"(b1))

// ---------------- prep kernels ------------------------------------------------
__global__ void prep_embed(const float* __restrict__ embed) {
    int c = blockIdx.x * 8 + (threadIdx.x >> 5);
    int lane = threadIdx.x & 31;
    const float4* e4 = (const float4*)embed;
    uint2* eb = (uint2*)g_ebf;
    float s = 0.f;
#pragma unroll
    for (int j = 0; j < 4; j++) {
        float4 v = e4[(size_t)c * (DD / 4) + j * 32 + lane];
        s += v.x * v.x + v.y * v.y + v.z * v.z + v.w * v.w;
        __nv_bfloat162 p0 = __floats2bfloat162_rn(v.x, v.y);
        __nv_bfloat162 p1 = __floats2bfloat162_rn(v.z, v.w);
        uint2 u;
        u.x = *reinterpret_cast<uint32_t*>(&p0);
        u.y = *reinterpret_cast<uint32_t*>(&p1);
        eb[(size_t)c * (DD / 4) + j * 32 + lane] = u;
    }
#pragma unroll
    for (int off = 16; off; off >>= 1) s += __shfl_xor_sync(0xffffffffu, s, off);
    if (lane == 0) g_half_e2[c] = 0.5f * s;

    int gid = blockIdx.x * 256 + threadIdx.x;
    if (gid < MM * SPLITS) g_cnt[gid] = 0;
}

__global__ void prep_x(const float* __restrict__ x) {
    int t = blockIdx.x * 8 + (threadIdx.x >> 5);
    int lane = threadIdx.x & 31;
    const float4* x4 = (const float4*)x;
    uint2* xb = (uint2*)g_xbf;
#pragma unroll
    for (int j = 0; j < 4; j++) {
        float4 v = x4[(size_t)t * (DD / 4) + j * 32 + lane];
        __nv_bfloat162 p0 = __floats2bfloat162_rn(v.x, v.y);
        __nv_bfloat162 p1 = __floats2bfloat162_rn(v.z, v.w);
        uint2 u;
        u.x = *reinterpret_cast<uint32_t*>(&p0);
        u.y = *reinterpret_cast<uint32_t*>(&p1);
        xb[(size_t)t * (DD / 4) + j * 32 + lane] = u;
    }
}

// ---------------- HMMA candidate pass -----------------------------------------
// grid (256, 4). CTA: 128 tokens x 2048-code split. 16 warps, warp tile 32x64.
#define SMEM_A   131072
#define SMEM_BCH 32768
#define SMEM_DYN (SMEM_A + 3 * SMEM_BCH)

__global__ __launch_bounds__(512, 1)
void vq_gemm(const int* __restrict__ ilen) {
    extern __shared__ char dsm[];
    __shared__ float sHE[NTILE];

    const int tid = threadIdx.x, lane = tid & 31, wid = tid >> 5;
    const int m0 = blockIdx.x * 128;
    if ((m0 & (SS - 1)) >= ilen[m0 >> 11]) return;   // fully masked tile
    const int split = blockIdx.y;
    const int split0 = split * CPS;

    const uint32_t sA = smem_u32(dsm);
    const uint32_t sB = sA + SMEM_A;

    {   // A prefetch: 128 tokens x 512 k, swizzled rows of 1KB
        const __nv_bfloat16* xb = g_xbf + (size_t)m0 * DD;
        for (int i = tid; i < 8192; i += 512) {
            int row = i >> 6, g = i & 63;
            uint32_t dst = sA + row * 1024 + ((g ^ (row & 7)) << 4);
            CP_ASYNC16(dst, xb + (size_t)row * DD + g * 8);
        }
    }
    auto prefB = [&](int gi) {   // 256 codes x 64 k = 32 KB
        const __nv_bfloat16* src0 =
            g_ebf + (size_t)(split0 + (gi >> 3) * NTILE) * DD + (gi & 7) * 64;
        uint32_t bb = sB + (gi % 3) * SMEM_BCH;
        for (int i = tid; i < 2048; i += 512) {
            int row = i >> 3, g = i & 7;
            uint32_t dst = bb + row * 128 + ((g ^ (row & 7)) << 4);
            CP_ASYNC16(dst, src0 + (size_t)row * DD + g * 8);
        }
    };
    prefB(0); CP_COMMIT;     // group 0: A + B0
    prefB(1); CP_COMMIT;     // group 1: B1

    const int wm = wid >> 2, wn = wid & 3;                 // 4 x 4 warp grid
    const int rA0 = wm * 32 + (lane & 15);
    const int kgA_off = lane >> 4;
    const int rB0 = wn * 64 + (lane & 7) + ((lane >> 4) << 3);
    const int kgB_off = (lane >> 3) & 1;

    float acc[2][8][4];
    float runmax[2][2] = {{RMINIT, RMINIT}, {RMINIT, RMINIT}};

    for (int gi = 0; gi < TOTCH; gi++) {
        const int nt = gi >> 3, ck = gi & 7;
        if (gi < TOTCH - 1) CP_WAIT(1); else CP_WAIT(0);
        __syncthreads();
        if (gi + 2 < TOTCH) { prefB(gi + 2); CP_COMMIT; }

        if (ck == 0) {
            if (tid < NTILE) sHE[tid] = g_half_e2[split0 + nt * NTILE + tid];
#pragma unroll
            for (int mt = 0; mt < 2; mt++)
#pragma unroll
                for (int j = 0; j < 8; j++)
#pragma unroll
                    for (int q = 0; q < 4; q++) acc[mt][j][q] = 0.f;
        }

        const uint32_t bb = sB + (gi % 3) * SMEM_BCH;

        // ---- ks loop with B-fragment double buffering ----
        uint32_t bfr[2][4][4];
        {   // prime B frags for ks=0
            const int kgB = kgB_off;
#pragma unroll
            for (int np = 0; np < 4; np++) {
                int row = rB0 + np * 16;
                LDSM4(bfr[0][np], bb + row * 128 + ((kgB ^ (row & 7)) << 4));
            }
        }
#pragma unroll
        for (int ks = 0; ks < 4; ks++) {
            const int cur = ks & 1;
            if (ks < 3) {                       // prefetch B for ks+1
                const int kgB = (ks + 1) * 2 + kgB_off;
#pragma unroll
                for (int np = 0; np < 4; np++) {
                    int row = rB0 + np * 16;
                    LDSM4(bfr[cur ^ 1][np], bb + row * 128 + ((kgB ^ (row & 7)) << 4));
                }
            }
            uint32_t a[2][4];
            const int kgA = ck * 8 + ks * 2 + kgA_off;
#pragma unroll
            for (int mt = 0; mt < 2; mt++) {
                int row = rA0 + mt * 16;
                LDSM4(a[mt], sA + row * 1024 + ((kgA ^ (row & 7)) << 4));
            }
#pragma unroll
            for (int mt = 0; mt < 2; mt++)
#pragma unroll
                for (int np = 0; np < 4; np++) {
                    MMA16816(acc[mt][np * 2],     a[mt], bfr[cur][np][0], bfr[cur][np][1]);
                    MMA16816(acc[mt][np * 2 + 1], a[mt], bfr[cur][np][2], bfr[cur][np][3]);
                }
        }

        if (ck == 7) {   // epilogue: two passes over acc, sHE read inline (no arrays)
            const int c0 = split0 + nt * NTILE;
            const int colb = wn * 64 + (lane & 3) * 2;
#pragma unroll
            for (int mt = 0; mt < 2; mt++)
#pragma unroll
                for (int hh = 0; hh < 2; hh++) {
                    float m = runmax[mt][hh];
#pragma unroll
                    for (int n8 = 0; n8 < 8; n8++) {
                        m = fmaxf(m, acc[mt][n8][hh * 2]     - sHE[colb + n8 * 8]);
                        m = fmaxf(m, acc[mt][n8][hh * 2 + 1] - sHE[colb + n8 * 8 + 1]);
                    }
                    m = fmaxf(m, __shfl_xor_sync(0xffffffffu, m, 1));
                    m = fmaxf(m, __shfl_xor_sync(0xffffffffu, m, 2));
                    runmax[mt][hh] = m;
                    const float thr = m - TAU;
                    const int row = m0 + wm * 32 + mt * 16 + hh * 8 + (lane >> 2);
#pragma unroll
                    for (int n8 = 0; n8 < 8; n8++)
#pragma unroll
                        for (int par = 0; par < 2; par++) {
                            float v = acc[mt][n8][hh * 2 + par] - sHE[colb + n8 * 8 + par];
                            if (v >= thr) {
                                int pos = atomicAdd(&g_cnt[(size_t)row * SPLITS + split], 1);
                                if (pos < CAND)
                                    g_cand[((size_t)row * SPLITS + split) * CAND + pos] =
                                        c0 + colb + n8 * 8 + par;
                            }
                        }
                }
        }
    }
}

// ---------------- exact fp32 rescore + gather ----------------------------------
__global__ __launch_bounds__(256)
void vq_rescore(const float* __restrict__ x, const int* __restrict__ ilen,
                const float* __restrict__ embed,
                float* __restrict__ outq, float* __restrict__ outi) {
    const int wid = threadIdx.x >> 5, lane = threadIdx.x & 31;
    const int t = blockIdx.x * 8 + wid;
    const int s = t & (SS - 1);
    const int len = ilen[t >> 11];
    float4* oq = (float4*)outq;

    if (s >= len) {
        float4 z = make_float4(0.f, 0.f, 0.f, 0.f);
#pragma unroll
        for (int j = 0; j < 4; j++) oq[(size_t)t * (DD / 4) + j * 32 + lane] = z;
        if (outi && lane == 0) outi[t] = -1.0f;
        return;
    }

    const float4* x4 = (const float4*)x;
    const float4* e4 = (const float4*)embed;
    float4 xr[4];
#pragma unroll
    for (int j = 0; j < 4; j++) xr[j] = x4[(size_t)t * (DD / 4) + j * 32 + lane];

    // gather candidate list for this token into registers-ish local walk,
    // processing PAIRS of candidates to double memory-level parallelism.
    float best = -3.402823466e38f;
    int bi = 0;
#pragma unroll 1
    for (int sp = 0; sp < SPLITS; sp++) {
        int cn = g_cnt[(size_t)t * SPLITS + sp];
        if (cn > CAND) cn = CAND;
        const int* cl = &g_cand[((size_t)t * SPLITS + sp) * CAND];
        int k = 0;
#pragma unroll 1
        for (; k + 1 < cn; k += 2) {
            int i0 = cl[k], i1 = cl[k + 1];
            float a0 = 0.f, a1 = 0.f;
#pragma unroll
            for (int j = 0; j < 4; j++) {
                float4 e0 = e4[(size_t)i0 * (DD / 4) + j * 32 + lane];
                float4 e1 = e4[(size_t)i1 * (DD / 4) + j * 32 + lane];
                a0 += xr[j].x * e0.x + xr[j].y * e0.y + xr[j].z * e0.z + xr[j].w * e0.w;
                a1 += xr[j].x * e1.x + xr[j].y * e1.y + xr[j].z * e1.z + xr[j].w * e1.w;
            }
#pragma unroll
            for (int off = 16; off; off >>= 1) {
                a0 += __shfl_xor_sync(0xffffffffu, a0, off);
                a1 += __shfl_xor_sync(0xffffffffu, a1, off);
            }
            float s0 = a0 - g_half_e2[i0];
            float s1 = a1 - g_half_e2[i1];
            if (s0 > best || (s0 == best && i0 < bi)) { best = s0; bi = i0; }
            if (s1 > best || (s1 == best && i1 < bi)) { best = s1; bi = i1; }
        }
        if (k < cn) {
            int i0 = cl[k];
            float a0 = 0.f;
#pragma unroll
            for (int j = 0; j < 4; j++) {
                float4 e0 = e4[(size_t)i0 * (DD / 4) + j * 32 + lane];
                a0 += xr[j].x * e0.x + xr[j].y * e0.y + xr[j].z * e0.z + xr[j].w * e0.w;
            }
#pragma unroll
            for (int off = 16; off; off >>= 1) a0 += __shfl_xor_sync(0xffffffffu, a0, off);
            float s0 = a0 - g_half_e2[i0];
            if (s0 > best || (s0 == best && i0 < bi)) { best = s0; bi = i0; }
        }
    }
#pragma unroll
    for (int j = 0; j < 4; j++)
        oq[(size_t)t * (DD / 4) + j * 32 + lane] = e4[(size_t)bi * (DD / 4) + j * 32 + lane];
    if (outi && lane == 0) outi[t] = (float)bi;
}

// ---------------- launch --------------------------------------------------------
extern "C" void kernel_launch(void* const* d_in, const int* in_sizes, int n_in,
                              void* d_out, int out_size) {
    const float* xp = nullptr;
    const int* lp = nullptr;
    const float* ep = nullptr;
    for (int i = 0; i < n_in; i++) {
        if (in_sizes[i] == MM * DD)      xp = (const float*)d_in[i];
        else if (in_sizes[i] == CC * DD) ep = (const float*)d_in[i];
        else if (in_sizes[i] == BB)      lp = (const int*)d_in[i];
    }
    float* oq = (float*)d_out;
    float* oi = (out_size >= (int)((size_t)MM * DD + MM)) ? oq + (size_t)MM * DD : nullptr;

    cudaFuncSetAttribute(vq_gemm, cudaFuncAttributeMaxDynamicSharedMemorySize, SMEM_DYN);

    prep_embed<<<CC / 8, 256>>>(ep);
    prep_x<<<MM / 8, 256>>>(xp);
    vq_gemm<<<dim3(256, SPLITS), 512, SMEM_DYN>>>(lp);
    vq_rescore<<<MM / 8, 256>>>(xp, lp, ep, oq, oi);
}